// round 11
// baseline (speedup 1.0000x reference)
#include <cuda_runtime.h>

// PlaneValidator: symmetric-chamfer between 1024 points and their per-plane
// reflections, then per-batch conf ranking + angular NMS.  Single fused kernel.
//
//  - D[n,m] = |p_n - r_m|^2 is SYMMETRIC  ->  sde = 2 * mean_n min_m D.
//  - row-min of D = p2 + min_m (R2[m] - 2 p.r_m).
//  - 4 ROWS/THREAD: each broadcast LDS.128 feeds 12 FFMA + 4 FMNMX of work,
//    so the 29-cyc shared-load latency is hidden by same-warp compute.
//    2 blocks per (b,h) (512-col halves), 256 thr; per-bh combine then the
//    last combiner runs the warp-parallel finalize.

#define NB 4
#define NPTS 1024
#define NH 16
#define THREADS 256
#define ROWS 4                  // rows per thread
#define HALF 512                // columns per block
#define NBLOCKS (NB * NH * 2)   // 128

#define COS_THR 0.8660254037844387f
#define FULL 0xFFFFFFFFu
#define FINF 3.4e38f

__device__ float g_rowmin[NBLOCKS * NPTS];  // per-block partial row minima (+p2)
__device__ float g_part[NB * NH];           // per-bh raw sums of row minima
__device__ int   g_cnt_bh[NB * NH];         // 2-arrival counters (self-resetting)
__device__ int   g_cnt_fin = 0;             // 64-arrival counter (self-resetting)

__global__ __launch_bounds__(THREADS, 1) void plane_validator_kernel(
        const float* __restrict__ pts, const float* __restrict__ ypred,
        const int* __restrict__ thr_ptr, float* __restrict__ out) {
    const int bid = blockIdx.x;
    const int bh  = bid >> 1;          // (b,h) pair
    const int ch  = bid & 1;           // column half
    const int t   = threadIdx.x;

    // ---------------- chamfer phase ----------------
    const float* yp = ypred + bh * 4;
    const float nx = yp[0], ny = yp[1], nz = yp[2], dpl = yp[3];
    const float inv = 1.0f / sqrtf(nx * nx + ny * ny + nz * nz);
    const float nhx = nx * inv, nhy = ny * inv, nhz = nz * inv;
    const float dh  = dpl * inv;

    const float* pb = pts + (bh >> 4) * (NPTS * 3);

    // This block's 512-column half: reflections as float4(-2r, |r|^2).
    // +2 pad entries so the distance-2 prefetch rotation needs no guard.
    __shared__ float4 sB[HALF + 2];
    for (int i = t; i < HALF; i += THREADS) {
        int g = ch * HALF + i;
        float px = pb[g * 3 + 0], py = pb[g * 3 + 1], pz = pb[g * 3 + 2];
        float proj = fmaf(px, nhx, fmaf(py, nhy, fmaf(pz, nhz, dh)));
        float s = -2.0f * proj;
        float rx = fmaf(s, nhx, px);
        float ry = fmaf(s, nhy, py);
        float rz = fmaf(s, nhz, pz);
        float r2 = fmaf(rx, rx, fmaf(ry, ry, rz * rz));
        sB[i] = make_float4(-2.0f * rx, -2.0f * ry, -2.0f * rz, r2);
    }
    if (t < 2) sB[HALF + t] = make_float4(0.f, 0.f, 0.f, 0.f);

    // This thread's 4 rows (plain points) + squared norms
    float ax[ROWS], ay[ROWS], az[ROWS], p2[ROWS];
#pragma unroll
    for (int k = 0; k < ROWS; k++) {
        int r = k * THREADS + t;
        float px = pb[r * 3 + 0], py = pb[r * 3 + 1], pz = pb[r * 3 + 2];
        ax[k] = px; ay[k] = py; az[k] = pz;
        p2[k] = fmaf(px, px, fmaf(py, py, pz * pz));
    }
    __syncthreads();

    // e_m = R2[m] - 2 p.r_m ; row-min of D = p2 + min e.
    // 8 accumulators (4 rows x even/odd col) = 8 independent FMNMX chains.
    float bA[ROWS], bB[ROWS];
#pragma unroll
    for (int k = 0; k < ROWS; k++) { bA[k] = FINF; bB[k] = FINF; }

    float4 qa = sB[0], qb = sB[1];    // distance-2 prefetch rotation
#pragma unroll 8
    for (int m = 0; m < HALF; m += 2) {
        float4 na = sB[m + 2];        // prefetch next pair (pad-safe)
        float4 nb = sB[m + 3];
#pragma unroll
        for (int k = 0; k < ROWS; k++) {
            float ea = fmaf(ax[k], qa.x, fmaf(ay[k], qa.y, fmaf(az[k], qa.z, qa.w)));
            float eb = fmaf(ax[k], qb.x, fmaf(ay[k], qb.y, fmaf(az[k], qb.z, qb.w)));
            bA[k] = fminf(bA[k], ea);
            bB[k] = fminf(bB[k], eb);
        }
        qa = na; qb = nb;
    }

    // min(e)+p2 = min(e+p2): safe to min-combine across halves later.
    float v[ROWS];
#pragma unroll
    for (int k = 0; k < ROWS; k++) {
        v[k] = fminf(bA[k], bB[k]) + p2[k];
        g_rowmin[bid * NPTS + k * THREADS + t] = v[k];
    }
    __threadfence();            // each thread publishes its own stores
    __syncthreads();            // all fences done before arrival

    __shared__ int s_flag;
    if (t == 0) {
        int old = atomicAdd(&g_cnt_bh[bh], 1);
        s_flag = (old == 1);    // second arriver combines
    }
    __syncthreads();
    if (!s_flag) return;

    // ---------------- combine phase (one block per bh) ----------------
    __threadfence();            // acquire peer's published rowmins
    const int peer = bid ^ 1;
    volatile float* rm = g_rowmin;
    float s = 0.0f;
#pragma unroll
    for (int k = 0; k < ROWS; k++) {
        float pv = rm[peer * NPTS + k * THREADS + t];
        s += fminf(v[k], pv);
    }

#pragma unroll
    for (int o = 16; o > 0; o >>= 1)
        s += __shfl_down_sync(FULL, s, o);

    __shared__ float wsum[THREADS / 32];
    if ((t & 31) == 0) wsum[t >> 5] = s;
    __syncthreads();
    if (t == 0) {
        float tot = 0.0f;
#pragma unroll
        for (int i = 0; i < THREADS / 32; i++) tot += wsum[i];
        g_part[bh] = tot;            // raw sum of 1024 row-mins
        g_cnt_bh[bh] = 0;            // reset pair counter for next replay
        __threadfence();
        int old2 = atomicAdd(&g_cnt_fin, 1);
        s_flag = (old2 == NB * NH - 1);
        if (old2 == NB * NH - 1) g_cnt_fin = 0;   // reset for next replay
    }
    __syncthreads();
    if (!s_flag) return;

    // ---------------- finalize phase (last combiner; lanes 0..63) ----------------
    __shared__ float s_ex[8][64];   // exchange: nx,ny,nz,px,py,pz,cf,sd by sorted pos

    const int l = t;
    float v_nx = 0, v_ny = 0, v_nz = 0, v_px = 0, v_py = 0, v_pz = 0, v_cf = 0, v_sd = 0;
    int pos = l & 15, b = l >> 4;

    if (l < 64) {
        // threshold: decode int32 vs float32 bit pattern defensively
        int tv = thr_ptr[0];
        float tf = __int_as_float(tv);
        float thr = (tf >= 1e-6f && tf <= 1e9f) ? tf : (float)tv;

        const float* yq = ypred + l * 4;
        float qx = yq[0], qy = yq[1], qz = yq[2], qd = yq[3];
        float qi = 1.0f / sqrtf(qx * qx + qy * qy + qz * qz);
        v_nx = qx * qi; v_ny = qy * qi; v_nz = qz * qi;
        float qdh = qd * qi;
        v_px = -qdh * v_nx; v_py = -qdh * v_ny; v_pz = -qdh * v_nz;

        // sde = 2 * mean(row mins)   (D symmetric)
        volatile float* gp = g_part;
        v_sd = gp[l] * (2.0f / (float)NPTS);

        // group min/max over 16 lanes
        float mn = v_sd, mx = v_sd;
#pragma unroll
        for (int o = 8; o > 0; o >>= 1) {
            mn = fminf(mn, __shfl_xor_sync(FULL, mn, o, 16));
            mx = fmaxf(mx, __shfl_xor_sync(FULL, mx, o, 16));
        }
        v_cf = 1.0f - (v_sd - mn) / (mx - mn);

        // stable descending rank (== stable argsort(-cf))
        int rank = 0;
#pragma unroll
        for (int j = 0; j < NH; j++) {
            float cfj = __shfl_sync(FULL, v_cf, j, 16);
            rank += (cfj > v_cf) || (cfj == v_cf && j < pos);
        }
        int slot = b * NH + rank;
        s_ex[0][slot] = v_nx; s_ex[1][slot] = v_ny; s_ex[2][slot] = v_nz;
        s_ex[3][slot] = v_px; s_ex[4][slot] = v_py; s_ex[5][slot] = v_pz;
        s_ex[6][slot] = v_cf; s_ex[7][slot] = v_sd;
        v_cf = thr;  // carry thr across the barrier
    }
    __syncthreads();
    if (l >= 64) return;

    float thr = v_cf;
    v_nx = s_ex[0][l]; v_ny = s_ex[1][l]; v_nz = s_ex[2][l];
    v_px = s_ex[3][l]; v_py = s_ex[4][l]; v_pz = s_ex[5][l];
    v_cf = s_ex[6][l]; v_sd = s_ex[7][l];

    // sequential NMS over sorted positions, live keep bits
    int keep = (v_sd <= thr);
#pragma unroll
    for (int i = 0; i < NH; i++) {
        int   ki  = __shfl_sync(FULL, keep, i, 16);
        float inx = __shfl_sync(FULL, v_nx, i, 16);
        float iny = __shfl_sync(FULL, v_ny, i, 16);
        float inz = __shfl_sync(FULL, v_nz, i, 16);
        float dt = inx * v_nx + iny * v_ny + inz * v_nz;
        if (ki && pos > i && dt > COS_THR) keep = 0;
    }

    // stable partition destination: kept first (in order), dropped after (in order)
    unsigned ball = __ballot_sync(FULL, keep);
    unsigned seg = (ball >> (l & 16)) & 0xFFFFu;
    int kept_before = __popc(seg & ((1u << pos) - 1));
    int total_kept  = __popc(seg);
    int dest = keep ? kept_before : total_kept + (pos - kept_before);

    float* o = out + (b * NH + dest) * 8;
    float4 r0 = keep ? make_float4(v_nx, v_ny, v_nz, v_px) : make_float4(0, 0, 0, 0);
    float4 r1 = keep ? make_float4(v_py, v_pz, v_cf, v_sd) : make_float4(0, 0, 0, 0);
    ((float4*)o)[0] = r0;
    ((float4*)o)[1] = r1;
}

extern "C" void kernel_launch(void* const* d_in, const int* in_sizes, int n_in,
                              void* d_out, int out_size) {
    const float* pts = nullptr;    // 12288 elems
    const float* ypred = nullptr;  // 256 elems
    const int* thr = nullptr;      // 1 elem
    for (int i = 0; i < n_in; i++) {
        if (in_sizes[i] == NB * NPTS * 3)    pts   = (const float*)d_in[i];
        else if (in_sizes[i] == NB * NH * 4) ypred = (const float*)d_in[i];
        else if (in_sizes[i] == 1)           thr   = (const int*)d_in[i];
    }
    float* out = (float*)d_out;

    plane_validator_kernel<<<NBLOCKS, THREADS>>>(pts, ypred, thr, out);
}

// round 12
// speedup vs baseline: 1.0093x; 1.0093x over previous
#include <cuda_runtime.h>

// PlaneValidator: symmetric-chamfer between 1024 points and their per-plane
// reflections, then per-batch conf ranking + angular NMS.  Single fused kernel.
//
//  - D[n,m] = |p_n - r_m|^2 is SYMMETRIC  ->  sde = 2 * mean_n min_m D.
//  - row-min of D = p2 + min_m (R2[m] - 2 p.r_m).
//  - 4 ROWS/THREAD x point-pair f32x2 packing: per 2 cols x 4 rows (8 pairs)
//    = 2 LDS.128 + 12 FFMA2 + 8 FMNMX (2.75 issues/pair), no prefetch MOVs —
//    each broadcast load feeds 24+ cycles of dependent work (latency hidden).
//  - 2 blocks per (b,h) (512-col halves), 256 thr; per-bh combine, last
//    combiner runs the warp-parallel finalize.

#define NB 4
#define NPTS 1024
#define NH 16
#define THREADS 256
#define ROWS 4                  // rows per thread
#define HALF 512                // columns per block
#define NBLOCKS (NB * NH * 2)   // 128

#define COS_THR 0.8660254037844387f
#define FULL 0xFFFFFFFFu
#define FINF 3.4e38f

__device__ float g_rowmin[NBLOCKS * NPTS];  // per-block partial row minima (+p2)
__device__ float g_part[NB * NH];           // per-bh raw sums of row minima
__device__ int   g_cnt_bh[NB * NH];         // 2-arrival counters (self-resetting)
__device__ int   g_cnt_fin = 0;             // 64-arrival counter (self-resetting)

__device__ __forceinline__ unsigned long long fma2(
        unsigned long long a, unsigned long long b, unsigned long long c) {
    unsigned long long d;
    asm("fma.rn.f32x2 %0, %1, %2, %3;" : "=l"(d) : "l"(a), "l"(b), "l"(c));
    return d;
}
__device__ __forceinline__ unsigned long long pack2(float lo, float hi) {
    unsigned long long d;
    asm("mov.b64 %0, {%1, %2};" : "=l"(d) : "f"(lo), "f"(hi));
    return d;
}
__device__ __forceinline__ void unpack2(unsigned long long v, float& lo, float& hi) {
    asm("mov.b64 {%0, %1}, %2;" : "=f"(lo), "=f"(hi) : "l"(v));
}

__global__ __launch_bounds__(THREADS, 1) void plane_validator_kernel(
        const float* __restrict__ pts, const float* __restrict__ ypred,
        const int* __restrict__ thr_ptr, float* __restrict__ out) {
    const int bid = blockIdx.x;
    const int bh  = bid >> 1;          // (b,h) pair
    const int ch  = bid & 1;           // column half
    const int t   = threadIdx.x;

    // ---------------- chamfer phase ----------------
    const float* yp = ypred + bh * 4;
    const float nx = yp[0], ny = yp[1], nz = yp[2], dpl = yp[3];
    const float inv = 1.0f / sqrtf(nx * nx + ny * ny + nz * nz);
    const float nhx = nx * inv, nhy = ny * inv, nhz = nz * inv;
    const float dh  = dpl * inv;

    const float* pb = pts + (bh >> 4) * (NPTS * 3);

    // Point-pair packed column tile (8 KB):
    //   word 2k   = { {-2rx_p0,-2rx_p1}, {-2ry_p0,-2ry_p1} }
    //   word 2k+1 = { {-2rz_p0,-2rz_p1}, { r2_p0 , r2_p1 } }   (p0=2k, p1=2k+1 local)
    // Staged scalar: local point i -> floats at sF[(i>>1)*8 + c*2 + (i&1)].
    __shared__ ulonglong2 sB[HALF];
    {
        float* sF = (float*)sB;
        for (int i = t; i < HALF; i += THREADS) {
            int g = ch * HALF + i;                  // global point index
            float px = pb[g * 3 + 0], py = pb[g * 3 + 1], pz = pb[g * 3 + 2];
            float proj = fmaf(px, nhx, fmaf(py, nhy, fmaf(pz, nhz, dh)));
            float s = -2.0f * proj;
            float rx = fmaf(s, nhx, px);
            float ry = fmaf(s, nhy, py);
            float rz = fmaf(s, nhz, pz);
            float r2 = fmaf(rx, rx, fmaf(ry, ry, rz * rz));
            int base = (i >> 1) * 8 + (i & 1);
            sF[base + 0] = -2.0f * rx;
            sF[base + 2] = -2.0f * ry;
            sF[base + 4] = -2.0f * rz;
            sF[base + 6] = r2;
        }
    }

    // This thread's 4 rows (plain points): coords broadcast into both f32x2 lanes
    float p2[ROWS];
    unsigned long long ax2[ROWS], ay2[ROWS], az2[ROWS];
#pragma unroll
    for (int k = 0; k < ROWS; k++) {
        int r = k * THREADS + t;
        float px = pb[r * 3 + 0], py = pb[r * 3 + 1], pz = pb[r * 3 + 2];
        ax2[k] = pack2(px, px);
        ay2[k] = pack2(py, py);
        az2[k] = pack2(pz, pz);
        p2[k] = fmaf(px, px, fmaf(py, py, pz * pz));
    }
    __syncthreads();

    // e_{p0,p1} = {R2 - 2 p.r} for 2 points x 4 rows per body.
    // 8 independent min chains (row x lane).
    float bLo[ROWS], bHi[ROWS];
#pragma unroll
    for (int k = 0; k < ROWS; k++) { bLo[k] = FINF; bHi[k] = FINF; }

#pragma unroll 4
    for (int m = 0; m < HALF / 2; m++) {
        ulonglong2 u0 = sB[2 * m];       // {xx, yy}
        ulonglong2 u1 = sB[2 * m + 1];   // {zz, rr}
#pragma unroll
        for (int k = 0; k < ROWS; k++) {
            unsigned long long e = fma2(ax2[k], u0.x,
                                   fma2(ay2[k], u0.y,
                                   fma2(az2[k], u1.x, u1.y)));
            float elo, ehi;
            unpack2(e, elo, ehi);
            bLo[k] = fminf(bLo[k], elo);
            bHi[k] = fminf(bHi[k], ehi);
        }
    }

    // min(e)+p2 = min(e+p2): safe to min-combine across halves later.
    float v[ROWS];
#pragma unroll
    for (int k = 0; k < ROWS; k++) {
        v[k] = fminf(bLo[k], bHi[k]) + p2[k];
        g_rowmin[bid * NPTS + k * THREADS + t] = v[k];
    }
    __threadfence();            // each thread publishes its own stores
    __syncthreads();            // all fences done before arrival

    __shared__ int s_flag;
    if (t == 0) {
        int old = atomicAdd(&g_cnt_bh[bh], 1);
        s_flag = (old == 1);    // second arriver combines
    }
    __syncthreads();
    if (!s_flag) return;

    // ---------------- combine phase (one block per bh) ----------------
    __threadfence();            // acquire peer's published rowmins
    const int peer = bid ^ 1;
    volatile float* rm = g_rowmin;
    float s = 0.0f;
#pragma unroll
    for (int k = 0; k < ROWS; k++) {
        float pv = rm[peer * NPTS + k * THREADS + t];
        s += fminf(v[k], pv);
    }

#pragma unroll
    for (int o = 16; o > 0; o >>= 1)
        s += __shfl_down_sync(FULL, s, o);

    __shared__ float wsum[THREADS / 32];
    if ((t & 31) == 0) wsum[t >> 5] = s;
    __syncthreads();
    if (t == 0) {
        float tot = 0.0f;
#pragma unroll
        for (int i = 0; i < THREADS / 32; i++) tot += wsum[i];
        g_part[bh] = tot;            // raw sum of 1024 row-mins
        g_cnt_bh[bh] = 0;            // reset pair counter for next replay
        __threadfence();
        int old2 = atomicAdd(&g_cnt_fin, 1);
        s_flag = (old2 == NB * NH - 1);
        if (old2 == NB * NH - 1) g_cnt_fin = 0;   // reset for next replay
    }
    __syncthreads();
    if (!s_flag) return;

    // ---------------- finalize phase (last combiner; lanes 0..63) ----------------
    __shared__ float s_ex[8][64];   // exchange: nx,ny,nz,px,py,pz,cf,sd by sorted pos

    const int l = t;
    float v_nx = 0, v_ny = 0, v_nz = 0, v_px = 0, v_py = 0, v_pz = 0, v_cf = 0, v_sd = 0;
    int pos = l & 15, b = l >> 4;

    if (l < 64) {
        // threshold: decode int32 vs float32 bit pattern defensively
        int tv = thr_ptr[0];
        float tf = __int_as_float(tv);
        float thr = (tf >= 1e-6f && tf <= 1e9f) ? tf : (float)tv;

        const float* yq = ypred + l * 4;
        float qx = yq[0], qy = yq[1], qz = yq[2], qd = yq[3];
        float qi = 1.0f / sqrtf(qx * qx + qy * qy + qz * qz);
        v_nx = qx * qi; v_ny = qy * qi; v_nz = qz * qi;
        float qdh = qd * qi;
        v_px = -qdh * v_nx; v_py = -qdh * v_ny; v_pz = -qdh * v_nz;

        // sde = 2 * mean(row mins)   (D symmetric)
        volatile float* gp = g_part;
        v_sd = gp[l] * (2.0f / (float)NPTS);

        // group min/max over 16 lanes
        float mn = v_sd, mx = v_sd;
#pragma unroll
        for (int o = 8; o > 0; o >>= 1) {
            mn = fminf(mn, __shfl_xor_sync(FULL, mn, o, 16));
            mx = fmaxf(mx, __shfl_xor_sync(FULL, mx, o, 16));
        }
        v_cf = 1.0f - (v_sd - mn) / (mx - mn);

        // stable descending rank (== stable argsort(-cf))
        int rank = 0;
#pragma unroll
        for (int j = 0; j < NH; j++) {
            float cfj = __shfl_sync(FULL, v_cf, j, 16);
            rank += (cfj > v_cf) || (cfj == v_cf && j < pos);
        }
        int slot = b * NH + rank;
        s_ex[0][slot] = v_nx; s_ex[1][slot] = v_ny; s_ex[2][slot] = v_nz;
        s_ex[3][slot] = v_px; s_ex[4][slot] = v_py; s_ex[5][slot] = v_pz;
        s_ex[6][slot] = v_cf; s_ex[7][slot] = v_sd;
        v_cf = thr;  // carry thr across the barrier
    }
    __syncthreads();
    if (l >= 64) return;

    float thr = v_cf;
    v_nx = s_ex[0][l]; v_ny = s_ex[1][l]; v_nz = s_ex[2][l];
    v_px = s_ex[3][l]; v_py = s_ex[4][l]; v_pz = s_ex[5][l];
    v_cf = s_ex[6][l]; v_sd = s_ex[7][l];

    // sequential NMS over sorted positions, live keep bits
    int keep = (v_sd <= thr);
#pragma unroll
    for (int i = 0; i < NH; i++) {
        int   ki  = __shfl_sync(FULL, keep, i, 16);
        float inx = __shfl_sync(FULL, v_nx, i, 16);
        float iny = __shfl_sync(FULL, v_ny, i, 16);
        float inz = __shfl_sync(FULL, v_nz, i, 16);
        float dt = inx * v_nx + iny * v_ny + inz * v_nz;
        if (ki && pos > i && dt > COS_THR) keep = 0;
    }

    // stable partition destination: kept first (in order), dropped after (in order)
    unsigned ball = __ballot_sync(FULL, keep);
    unsigned seg = (ball >> (l & 16)) & 0xFFFFu;
    int kept_before = __popc(seg & ((1u << pos) - 1));
    int total_kept  = __popc(seg);
    int dest = keep ? kept_before : total_kept + (pos - kept_before);

    float* o = out + (b * NH + dest) * 8;
    float4 r0 = keep ? make_float4(v_nx, v_ny, v_nz, v_px) : make_float4(0, 0, 0, 0);
    float4 r1 = keep ? make_float4(v_py, v_pz, v_cf, v_sd) : make_float4(0, 0, 0, 0);
    ((float4*)o)[0] = r0;
    ((float4*)o)[1] = r1;
}

extern "C" void kernel_launch(void* const* d_in, const int* in_sizes, int n_in,
                              void* d_out, int out_size) {
    const float* pts = nullptr;    // 12288 elems
    const float* ypred = nullptr;  // 256 elems
    const int* thr = nullptr;      // 1 elem
    for (int i = 0; i < n_in; i++) {
        if (in_sizes[i] == NB * NPTS * 3)    pts   = (const float*)d_in[i];
        else if (in_sizes[i] == NB * NH * 4) ypred = (const float*)d_in[i];
        else if (in_sizes[i] == 1)           thr   = (const int*)d_in[i];
    }
    float* out = (float*)d_out;

    plane_validator_kernel<<<NBLOCKS, THREADS>>>(pts, ypred, thr, out);
}

// round 13
// speedup vs baseline: 1.0140x; 1.0047x over previous
#include <cuda_runtime.h>

// PlaneValidator: symmetric-chamfer between 1024 points and their per-plane
// reflections, then per-batch conf ranking + angular NMS.  Single fused kernel.
//
//  - D[n,m] = |p_n - r_m|^2 is SYMMETRIC  ->  sde = 2 * mean_n min_m D.
//  - row-min of D = p2 + min_m (R2[m] - 2 p.r_m).
//  - 4 rows/thread x point-pair f32x2 packing (R12) with asm-volatile ORDERED
//    load batching: 16 back-to-back LDS.128 per super-iteration (16 cols) so
//    the 29-cyc shared latency is covered by load-issue itself, independent of
//    ptxas scheduling.  LDS-return BW (128B/cyc/SM) becomes the binding pipe.
//  - 2 blocks per (b,h) (512-col halves), 256 thr; per-bh combine, last
//    combiner runs the warp-parallel finalize.

#define NB 4
#define NPTS 1024
#define NH 16
#define THREADS 256
#define ROWS 4                  // rows per thread
#define HALF 512                // columns per block
#define NBLOCKS (NB * NH * 2)   // 128

#define COS_THR 0.8660254037844387f
#define FULL 0xFFFFFFFFu
#define FINF 3.4e38f

__device__ float g_rowmin[NBLOCKS * NPTS];  // per-block partial row minima (+p2)
__device__ float g_part[NB * NH];           // per-bh raw sums of row minima
__device__ int   g_cnt_bh[NB * NH];         // 2-arrival counters (self-resetting)
__device__ int   g_cnt_fin = 0;             // 64-arrival counter (self-resetting)

__device__ __forceinline__ unsigned long long fma2(
        unsigned long long a, unsigned long long b, unsigned long long c) {
    unsigned long long d;
    asm("fma.rn.f32x2 %0, %1, %2, %3;" : "=l"(d) : "l"(a), "l"(b), "l"(c));
    return d;
}
__device__ __forceinline__ unsigned long long pack2(float lo, float hi) {
    unsigned long long d;
    asm("mov.b64 %0, {%1, %2};" : "=l"(d) : "f"(lo), "f"(hi));
    return d;
}
__device__ __forceinline__ void unpack2(unsigned long long v, float& lo, float& hi) {
    asm("mov.b64 {%0, %1}, %2;" : "=f"(lo), "=f"(hi) : "l"(v));
}

// Ordered 16B shared load into two u64 halves at a literal byte offset.
#define LDSV2(d0, d1, areg, OFFSTR) \
    asm volatile("ld.shared.v2.b64 {%0,%1}, [%2+" OFFSTR "];" \
                 : "=l"(d0), "=l"(d1) : "r"(areg))

__global__ __launch_bounds__(THREADS, 1) void plane_validator_kernel(
        const float* __restrict__ pts, const float* __restrict__ ypred,
        const int* __restrict__ thr_ptr, float* __restrict__ out) {
    const int bid = blockIdx.x;
    const int bh  = bid >> 1;          // (b,h) pair
    const int ch  = bid & 1;           // column half
    const int t   = threadIdx.x;

    // ---------------- chamfer phase ----------------
    const float* yp = ypred + bh * 4;
    const float nx = yp[0], ny = yp[1], nz = yp[2], dpl = yp[3];
    const float inv = 1.0f / sqrtf(nx * nx + ny * ny + nz * nz);
    const float nhx = nx * inv, nhy = ny * inv, nhz = nz * inv;
    const float dh  = dpl * inv;

    const float* pb = pts + (bh >> 4) * (NPTS * 3);

    // Point-pair packed column tile (8 KB):
    //   word 2k   = { {-2rx_p0,-2rx_p1}, {-2ry_p0,-2ry_p1} }
    //   word 2k+1 = { {-2rz_p0,-2rz_p1}, { r2_p0 , r2_p1 } }   (p0=2k, p1=2k+1 local)
    __shared__ ulonglong2 sB[HALF];
    {
        float* sF = (float*)sB;
        for (int i = t; i < HALF; i += THREADS) {
            int g = ch * HALF + i;                  // global point index
            float px = pb[g * 3 + 0], py = pb[g * 3 + 1], pz = pb[g * 3 + 2];
            float proj = fmaf(px, nhx, fmaf(py, nhy, fmaf(pz, nhz, dh)));
            float s = -2.0f * proj;
            float rx = fmaf(s, nhx, px);
            float ry = fmaf(s, nhy, py);
            float rz = fmaf(s, nhz, pz);
            float r2 = fmaf(rx, rx, fmaf(ry, ry, rz * rz));
            int base = (i >> 1) * 8 + (i & 1);
            sF[base + 0] = -2.0f * rx;
            sF[base + 2] = -2.0f * ry;
            sF[base + 4] = -2.0f * rz;
            sF[base + 6] = r2;
        }
    }

    // This thread's 4 rows (plain points): coords broadcast into both f32x2 lanes
    float p2[ROWS];
    unsigned long long ax2[ROWS], ay2[ROWS], az2[ROWS];
#pragma unroll
    for (int k = 0; k < ROWS; k++) {
        int r = k * THREADS + t;
        float px = pb[r * 3 + 0], py = pb[r * 3 + 1], pz = pb[r * 3 + 2];
        ax2[k] = pack2(px, px);
        ay2[k] = pack2(py, py);
        az2[k] = pack2(pz, pz);
        p2[k] = fmaf(px, px, fmaf(py, py, pz * pz));
    }
    __syncthreads();

    // Main loop: super-iteration = 16 columns = 8 packed bodies.
    // 16 ordered LDS.128 front-batched, then 8 x (4 rows) f32x2 chains.
    float bLo[ROWS], bHi[ROWS];
#pragma unroll
    for (int k = 0; k < ROWS; k++) { bLo[k] = FINF; bHi[k] = FINF; }

    unsigned a = (unsigned)__cvta_generic_to_shared(sB);
    for (int sup = 0; sup < HALF / 16; sup++) {     // 32 supers; a += 256B each
        unsigned long long X[8], Y[8], Z[8], W[8];
        LDSV2(X[0], Y[0], a, "0");   LDSV2(Z[0], W[0], a, "16");
        LDSV2(X[1], Y[1], a, "32");  LDSV2(Z[1], W[1], a, "48");
        LDSV2(X[2], Y[2], a, "64");  LDSV2(Z[2], W[2], a, "80");
        LDSV2(X[3], Y[3], a, "96");  LDSV2(Z[3], W[3], a, "112");
        LDSV2(X[4], Y[4], a, "128"); LDSV2(Z[4], W[4], a, "144");
        LDSV2(X[5], Y[5], a, "160"); LDSV2(Z[5], W[5], a, "176");
        LDSV2(X[6], Y[6], a, "192"); LDSV2(Z[6], W[6], a, "208");
        LDSV2(X[7], Y[7], a, "224"); LDSV2(Z[7], W[7], a, "240");
        a += 256;
#pragma unroll
        for (int j = 0; j < 8; j++) {
#pragma unroll
            for (int k = 0; k < ROWS; k++) {
                unsigned long long e = fma2(ax2[k], X[j],
                                       fma2(ay2[k], Y[j],
                                       fma2(az2[k], Z[j], W[j])));
                float elo, ehi;
                unpack2(e, elo, ehi);
                bLo[k] = fminf(bLo[k], elo);
                bHi[k] = fminf(bHi[k], ehi);
            }
        }
    }

    // min(e)+p2 = min(e+p2): safe to min-combine across halves later.
    float v[ROWS];
#pragma unroll
    for (int k = 0; k < ROWS; k++) {
        v[k] = fminf(bLo[k], bHi[k]) + p2[k];
        g_rowmin[bid * NPTS + k * THREADS + t] = v[k];
    }
    __threadfence();            // each thread publishes its own stores
    __syncthreads();            // all fences done before arrival

    __shared__ int s_flag;
    if (t == 0) {
        int old = atomicAdd(&g_cnt_bh[bh], 1);
        s_flag = (old == 1);    // second arriver combines
    }
    __syncthreads();
    if (!s_flag) return;

    // ---------------- combine phase (one block per bh) ----------------
    __threadfence();            // acquire peer's published rowmins
    const int peer = bid ^ 1;
    volatile float* rm = g_rowmin;
    float s = 0.0f;
#pragma unroll
    for (int k = 0; k < ROWS; k++) {
        float pv = rm[peer * NPTS + k * THREADS + t];
        s += fminf(v[k], pv);
    }

#pragma unroll
    for (int o = 16; o > 0; o >>= 1)
        s += __shfl_down_sync(FULL, s, o);

    __shared__ float wsum[THREADS / 32];
    if ((t & 31) == 0) wsum[t >> 5] = s;
    __syncthreads();
    if (t == 0) {
        float tot = 0.0f;
#pragma unroll
        for (int i = 0; i < THREADS / 32; i++) tot += wsum[i];
        g_part[bh] = tot;            // raw sum of 1024 row-mins
        g_cnt_bh[bh] = 0;            // reset pair counter for next replay
        __threadfence();
        int old2 = atomicAdd(&g_cnt_fin, 1);
        s_flag = (old2 == NB * NH - 1);
        if (old2 == NB * NH - 1) g_cnt_fin = 0;   // reset for next replay
    }
    __syncthreads();
    if (!s_flag) return;

    // ---------------- finalize phase (last combiner; lanes 0..63) ----------------
    __shared__ float s_ex[8][64];   // exchange: nx,ny,nz,px,py,pz,cf,sd by sorted pos

    const int l = t;
    float v_nx = 0, v_ny = 0, v_nz = 0, v_px = 0, v_py = 0, v_pz = 0, v_cf = 0, v_sd = 0;
    int pos = l & 15, b = l >> 4;

    if (l < 64) {
        // threshold: decode int32 vs float32 bit pattern defensively
        int tv = thr_ptr[0];
        float tf = __int_as_float(tv);
        float thr = (tf >= 1e-6f && tf <= 1e9f) ? tf : (float)tv;

        const float* yq = ypred + l * 4;
        float qx = yq[0], qy = yq[1], qz = yq[2], qd = yq[3];
        float qi = 1.0f / sqrtf(qx * qx + qy * qy + qz * qz);
        v_nx = qx * qi; v_ny = qy * qi; v_nz = qz * qi;
        float qdh = qd * qi;
        v_px = -qdh * v_nx; v_py = -qdh * v_ny; v_pz = -qdh * v_nz;

        // sde = 2 * mean(row mins)   (D symmetric)
        volatile float* gp = g_part;
        v_sd = gp[l] * (2.0f / (float)NPTS);

        // group min/max over 16 lanes
        float mn = v_sd, mx = v_sd;
#pragma unroll
        for (int o = 8; o > 0; o >>= 1) {
            mn = fminf(mn, __shfl_xor_sync(FULL, mn, o, 16));
            mx = fmaxf(mx, __shfl_xor_sync(FULL, mx, o, 16));
        }
        v_cf = 1.0f - (v_sd - mn) / (mx - mn);

        // stable descending rank (== stable argsort(-cf))
        int rank = 0;
#pragma unroll
        for (int j = 0; j < NH; j++) {
            float cfj = __shfl_sync(FULL, v_cf, j, 16);
            rank += (cfj > v_cf) || (cfj == v_cf && j < pos);
        }
        int slot = b * NH + rank;
        s_ex[0][slot] = v_nx; s_ex[1][slot] = v_ny; s_ex[2][slot] = v_nz;
        s_ex[3][slot] = v_px; s_ex[4][slot] = v_py; s_ex[5][slot] = v_pz;
        s_ex[6][slot] = v_cf; s_ex[7][slot] = v_sd;
        v_cf = thr;  // carry thr across the barrier
    }
    __syncthreads();
    if (l >= 64) return;

    float thr = v_cf;
    v_nx = s_ex[0][l]; v_ny = s_ex[1][l]; v_nz = s_ex[2][l];
    v_px = s_ex[3][l]; v_py = s_ex[4][l]; v_pz = s_ex[5][l];
    v_cf = s_ex[6][l]; v_sd = s_ex[7][l];

    // sequential NMS over sorted positions, live keep bits
    int keep = (v_sd <= thr);
#pragma unroll
    for (int i = 0; i < NH; i++) {
        int   ki  = __shfl_sync(FULL, keep, i, 16);
        float inx = __shfl_sync(FULL, v_nx, i, 16);
        float iny = __shfl_sync(FULL, v_ny, i, 16);
        float inz = __shfl_sync(FULL, v_nz, i, 16);
        float dt = inx * v_nx + iny * v_ny + inz * v_nz;
        if (ki && pos > i && dt > COS_THR) keep = 0;
    }

    // stable partition destination: kept first (in order), dropped after (in order)
    unsigned ball = __ballot_sync(FULL, keep);
    unsigned seg = (ball >> (l & 16)) & 0xFFFFu;
    int kept_before = __popc(seg & ((1u << pos) - 1));
    int total_kept  = __popc(seg);
    int dest = keep ? kept_before : total_kept + (pos - kept_before);

    float* o = out + (b * NH + dest) * 8;
    float4 r0 = keep ? make_float4(v_nx, v_ny, v_nz, v_px) : make_float4(0, 0, 0, 0);
    float4 r1 = keep ? make_float4(v_py, v_pz, v_cf, v_sd) : make_float4(0, 0, 0, 0);
    ((float4*)o)[0] = r0;
    ((float4*)o)[1] = r1;
}

extern "C" void kernel_launch(void* const* d_in, const int* in_sizes, int n_in,
                              void* d_out, int out_size) {
    const float* pts = nullptr;    // 12288 elems
    const float* ypred = nullptr;  // 256 elems
    const int* thr = nullptr;      // 1 elem
    for (int i = 0; i < n_in; i++) {
        if (in_sizes[i] == NB * NPTS * 3)    pts   = (const float*)d_in[i];
        else if (in_sizes[i] == NB * NH * 4) ypred = (const float*)d_in[i];
        else if (in_sizes[i] == 1)           thr   = (const int*)d_in[i];
    }
    float* out = (float*)d_out;

    plane_validator_kernel<<<NBLOCKS, THREADS>>>(pts, ypred, thr, out);
}